// round 2
// baseline (speedup 1.0000x reference)
#include <cuda_runtime.h>
#include <cstdint>

// Problem constants (fixed by reference_code)
#define NN     38333
#define EE     (38333 * 32)          // 1226656
#define VOCAB  39816
#define EMBD   62
#define SLOPE  0.01f

// ---------------- device scratch (static allocation only) ----------------
__device__ int   g_dtype;            // 0=int32, 1=int64, 2=float32
__device__ int   g_row[EE];
__device__ int   g_col[EE];
__device__ int   g_cnt[NN];
__device__ int   g_cursor[NN];
__device__ int   g_start[NN + 1];
__device__ float g_dinv[NN];
__device__ __align__(16) float2 g_sedge[EE];      // (row-as-bits, norm)
__device__ __align__(16) float  g_h0[(size_t)NN * 128];
__device__ __align__(16) float  g_hw[(size_t)NN * 64];
__device__ __align__(16) float  g_hb[(size_t)NN * 64];
__device__ float g_fcpart[128];

// ---------------- setup / sort pipeline ----------------
__global__ void setup_kernel() {
    int i = blockIdx.x * blockDim.x + threadIdx.x;
    if (i < NN) { g_cnt[i] = 0; g_cursor[i] = 0; }
    if (i < 128) g_fcpart[i] = 0.f;
    if (i == 0) g_dtype = 1;   // flags start: assume int64 & float both plausible
}

// Detect edge_index dtype. Samples are read at offsets valid for every layout.
//  - float32 check: value is a non-negative integer < NN when read as float
//    (int data read as float gives denormals which fail f==floorf(f) unless 0)
//  - int64 check: value in [0,NN) when read as int64 (int32 data packs two
//    ids -> hi word nonzero -> huge)
__device__ int g_okf, g_ok64;
__global__ void detect_init_kernel() { g_okf = 1; g_ok64 = 1; }
__global__ void detect_kernel(const void* eidx) {
    int t = blockIdx.x * blockDim.x + threadIdx.x;   // 4096 threads
    // float interpretation (element idx < 1.23M, valid for all layouts)
    const float* pf = (const float*)eidx;
    float f = pf[(size_t)t * 299];
    if (!(f >= 0.f && f < (float)NN && f == floorf(f))) atomicExch(&g_okf, 0);
    // int64 interpretation (byte offset <= 9.79MB, valid for all layouts)
    const long long* p8 = (const long long*)eidx;
    long long v = p8[(size_t)t * 299];
    if (v < 0 || v >= NN) atomicExch(&g_ok64, 0);
}
__global__ void detect_resolve_kernel() {
    g_dtype = g_okf ? 2 : (g_ok64 ? 1 : 0);
}

__global__ void convert_hist_kernel(const void* eidx) {
    int e = blockIdx.x * blockDim.x + threadIdx.x;
    if (e >= EE) return;
    int row, col;
    int dt = g_dtype;
    if (dt == 1) {
        const long long* p = (const long long*)eidx;
        row = (int)p[e]; col = (int)p[EE + e];
    } else if (dt == 0) {
        const int* p = (const int*)eidx;
        row = p[e]; col = p[EE + e];
    } else {
        const float* p = (const float*)eidx;
        row = (int)p[e]; col = (int)p[EE + e];
    }
    g_row[e] = row; g_col[e] = col;
    atomicAdd(&g_cnt[col], 1);
}

__global__ void dinv_kernel() {
    int i = blockIdx.x * blockDim.x + threadIdx.x;
    if (i < NN) g_dinv[i] = rsqrtf((float)g_cnt[i] + 1.0f);
}

// single-block scan of g_cnt -> g_start (exclusive)
__global__ void scan_kernel() {
    __shared__ int sm[1024];
    int t = threadIdx.x;
    const int CH = (NN + 1023) / 1024;               // 38
    int base = t * CH;
    int s = 0;
    for (int j = 0; j < CH; j++) { int idx = base + j; if (idx < NN) s += g_cnt[idx]; }
    sm[t] = s;
    __syncthreads();
    for (int off = 1; off < 1024; off <<= 1) {
        int v = (t >= off) ? sm[t - off] : 0;
        __syncthreads();
        sm[t] += v;
        __syncthreads();
    }
    int run = sm[t] - s;                             // exclusive offset
    for (int j = 0; j < CH; j++) {
        int idx = base + j;
        if (idx < NN) { g_start[idx] = run; run += g_cnt[idx]; }
    }
    if (t == 1023) g_start[NN] = sm[1023];
}

__global__ void scatter_kernel() {
    int e = blockIdx.x * blockDim.x + threadIdx.x;
    if (e >= EE) return;
    int col = g_col[e];
    int row = g_row[e];
    int pos = g_start[col] + atomicAdd(&g_cursor[col], 1);
    g_sedge[pos] = make_float2(__int_as_float(row), g_dinv[row] * g_dinv[col]);
}

// ---------------- feature build ----------------
__global__ void build_h0_kernel(const float* __restrict__ x, const float* __restrict__ emb) {
    int gw = (blockIdx.x * blockDim.x + threadIdx.x) >> 5;
    int lane = threadIdx.x & 31;
    if (gw >= NN) return;
    int i = gw;
    int id0 = (int)x[(size_t)i * 5 + 0];
    int id1 = (int)x[(size_t)i * 5 + 1];
    float* hr = g_h0 + (size_t)i * 128;
    for (int j = lane; j < EMBD; j += 32) {
        hr[j]        = emb[(size_t)id0 * EMBD + j];
        hr[EMBD + j] = emb[(size_t)id1 * EMBD + j];
    }
    if (lane < 3)  hr[124 + lane] = x[(size_t)i * 5 + 2 + lane];
    if (lane == 3) hr[127] = 0.f;
}

// ---------------- GEMM: hw = h @ W  (thread per row, W in smem broadcast) ----------------
template <int INP, int INR, int OUT>
__global__ void gemm_kernel(const float* __restrict__ h, const float* __restrict__ W,
                            float* __restrict__ hw) {
    __shared__ float Ws[INP * OUT];
    for (int idx = threadIdx.x; idx < INP * OUT; idx += blockDim.x)
        Ws[idx] = (idx < INR * OUT) ? W[idx] : 0.f;
    __syncthreads();
    int row = blockIdx.x * blockDim.x + threadIdx.x;
    if (row >= NN) return;
    float acc[OUT];
#pragma unroll
    for (int j = 0; j < OUT; j++) acc[j] = 0.f;
    const float* hr = h + (size_t)row * INP;
    for (int k = 0; k < INP; k += 4) {
        float4 hv = *reinterpret_cast<const float4*>(hr + k);
#pragma unroll
        for (int kk = 0; kk < 4; kk++) {
            float hx = (kk == 0) ? hv.x : (kk == 1) ? hv.y : (kk == 2) ? hv.z : hv.w;
#pragma unroll
            for (int j = 0; j < OUT; j += 4) {
                float4 w = *reinterpret_cast<const float4*>(&Ws[(k + kk) * OUT + j]);
                acc[j]     += hx * w.x;
                acc[j + 1] += hx * w.y;
                acc[j + 2] += hx * w.z;
                acc[j + 3] += hx * w.w;
            }
        }
    }
    float* o = hw + (size_t)row * OUT;
#pragma unroll
    for (int j = 0; j < OUT; j += 4)
        *reinterpret_cast<float4*>(o + j) = make_float4(acc[j], acc[j + 1], acc[j + 2], acc[j + 3]);
}

__device__ __forceinline__ float act_apply(float t, int ACT) {
    float l = (t >= 0.f) ? t : SLOPE * t;
    return (ACT == 1) ? (l + t) : l;
}

// ---------------- aggregation: out[i] = act(sum_in + hw[i]*dinv^2 + b), warp per node ----------------
template <int ACT>
__global__ void agg64_kernel(const float* __restrict__ hw, const float* __restrict__ b,
                             float* __restrict__ out) {
    int gw = (blockIdx.x * blockDim.x + threadIdx.x) >> 5;
    int lane = threadIdx.x & 31;
    if (gw >= NN) return;
    int i = gw;
    float2 acc = make_float2(0.f, 0.f);
    int s = g_start[i], e2 = g_start[i + 1];
    for (int e = s; e < e2; e++) {
        float2 rn = g_sedge[e];
        int row = __float_as_int(rn.x);
        float2 hv = *reinterpret_cast<const float2*>(&hw[(size_t)row * 64 + 2 * lane]);
        acc.x += hv.x * rn.y;
        acc.y += hv.y * rn.y;
    }
    float dv = g_dinv[i];
    float sn = dv * dv;
    float2 hs = *reinterpret_cast<const float2*>(&hw[(size_t)i * 64 + 2 * lane]);
    float tx = acc.x + hs.x * sn + b[2 * lane];
    float ty = acc.y + hs.y * sn + b[2 * lane + 1];
    float2 r = make_float2(act_apply(tx, ACT), act_apply(ty, ACT));
    *reinterpret_cast<float2*>(&out[(size_t)i * 64 + 2 * lane]) = r;
}

template <int ACT>
__global__ void agg32_kernel(const float* __restrict__ hw, const float* __restrict__ b,
                             float* __restrict__ out) {
    int gw = (blockIdx.x * blockDim.x + threadIdx.x) >> 5;
    int lane = threadIdx.x & 31;
    if (gw >= NN) return;
    int i = gw;
    float acc = 0.f;
    int s = g_start[i], e2 = g_start[i + 1];
    for (int e = s; e < e2; e++) {
        float2 rn = g_sedge[e];
        int row = __float_as_int(rn.x);
        acc += hw[(size_t)row * 32 + lane] * rn.y;
    }
    float dv = g_dinv[i];
    float t = acc + hw[(size_t)i * 32 + lane] * (dv * dv) + b[lane];
    out[(size_t)i * 32 + lane] = act_apply(t, ACT);
}

// ---------------- layer 5 (32 -> 1) ----------------
__global__ void gemm5_kernel(const float* __restrict__ h, const float* __restrict__ W5,
                             float* __restrict__ hw) {
    __shared__ float Ws[32];
    if (threadIdx.x < 32) Ws[threadIdx.x] = W5[threadIdx.x];
    __syncthreads();
    int i = blockIdx.x * blockDim.x + threadIdx.x;
    if (i >= NN) return;
    const float* hr = h + (size_t)i * 32;
    float a = 0.f;
#pragma unroll
    for (int k = 0; k < 32; k++) a += hr[k] * Ws[k];
    hw[i] = a;
}

__global__ void agg5_kernel(const float* __restrict__ hw, const float* __restrict__ b5,
                            float* __restrict__ v) {
    int gw = (blockIdx.x * blockDim.x + threadIdx.x) >> 5;
    int lane = threadIdx.x & 31;
    if (gw >= NN) return;
    int i = gw;
    float a = 0.f;
    int s = g_start[i], e2 = g_start[i + 1];
    for (int e = s + lane; e < e2; e += 32) {
        float2 rn = g_sedge[e];
        a += hw[__float_as_int(rn.x)] * rn.y;
    }
#pragma unroll
    for (int m = 16; m > 0; m >>= 1) a += __shfl_xor_sync(0xFFFFFFFFu, a, m);
    if (lane == 0) {
        float dv = g_dinv[i];
        float t = a + hw[i] * (dv * dv) + b5[0];
        v[i] = (t >= 0.f) ? t : SLOPE * t;
    }
}

// ---------------- final FC ----------------
__global__ void fc1_kernel(const float* __restrict__ v, const float* __restrict__ Wf1) {
    int j = threadIdx.x;           // 128
    int b = blockIdx.x;            // 128
    const int RP = (NN + 127) / 128;
    int r0 = b * RP;
    int r1 = (r0 + RP < NN) ? (r0 + RP) : NN;
    float acc = 0.f;
    for (int r = r0; r < r1; r++) acc += v[r] * Wf1[(size_t)r * 128 + j];
    atomicAdd(&g_fcpart[j], acc);
}

__global__ void fc2_kernel(const float* __restrict__ bf1, const float* __restrict__ Wf2,
                           const float* __restrict__ bf2, float* __restrict__ out) {
    __shared__ float o1[128];
    int j = threadIdx.x;
    float t = g_fcpart[j] + bf1[j];
    o1[j] = (t > 0.f) ? t : 0.f;
    __syncthreads();
    float acc = bf2[j];
    for (int k = 0; k < 128; k++) acc += o1[k] * Wf2[(size_t)k * 128 + j];
    out[j] = (acc > 0.f) ? acc : 0.f;
}

// ---------------- launcher ----------------
extern "C" void kernel_launch(void* const* d_in, const int* in_sizes, int n_in,
                              void* d_out, int out_size) {
    const float* x    = (const float*)d_in[0];
    const void*  eix  = d_in[1];
    const float* emb  = (const float*)d_in[2];
    const float* W1   = (const float*)d_in[3];
    const float* b1   = (const float*)d_in[4];
    const float* W2   = (const float*)d_in[5];
    const float* b2   = (const float*)d_in[6];
    const float* W3   = (const float*)d_in[7];
    const float* b3   = (const float*)d_in[8];
    const float* W4   = (const float*)d_in[9];
    const float* b4   = (const float*)d_in[10];
    const float* W5   = (const float*)d_in[11];
    const float* b5   = (const float*)d_in[12];
    const float* Wf1  = (const float*)d_in[13];
    const float* bf1  = (const float*)d_in[14];
    const float* Wf2  = (const float*)d_in[15];
    const float* bf2  = (const float*)d_in[16];
    float* out = (float*)d_out;

    // CRITICAL: __device__ symbols must be resolved to device addresses before
    // being passed as kernel arguments. (Passing the symbol directly from host
    // code passes the host shadow address — which on GB300 is ATS-dereferenceable
    // and silently reads host zeros.) cudaGetSymbolAddress is a non-stream,
    // non-allocating query: graph-capture legal.
    float *p_h0 = nullptr, *p_hw = nullptr, *p_hb = nullptr;
    cudaGetSymbolAddress((void**)&p_h0, g_h0);
    cudaGetSymbolAddress((void**)&p_hw, g_hw);
    cudaGetSymbolAddress((void**)&p_hb, g_hb);

    const int TB = 256;
    const int NB_N  = (NN + TB - 1) / TB;           // thread-per-node grids
    const int NB_E  = (EE + TB - 1) / TB;           // thread-per-edge grids
    const int NB_W  = (NN + 7) / 8;                 // warp-per-node grids (8 warps/block)

    setup_kernel<<<NB_N, TB>>>();
    detect_init_kernel<<<1, 1>>>();
    detect_kernel<<<16, 256>>>(eix);
    detect_resolve_kernel<<<1, 1>>>();
    convert_hist_kernel<<<NB_E, TB>>>(eix);
    dinv_kernel<<<NB_N, TB>>>();
    scan_kernel<<<1, 1024>>>();
    scatter_kernel<<<NB_E, TB>>>();

    build_h0_kernel<<<NB_W, TB>>>(x, emb);

    // L1: 127(->128 pad) -> 64, lrelu
    gemm_kernel<128, 127, 64><<<NB_N, TB>>>(p_h0, W1, p_hw);
    agg64_kernel<0><<<NB_W, TB>>>(p_hw, b1, p_hb);
    // L2: 64 -> 32, lrelu
    gemm_kernel<64, 64, 32><<<NB_N, TB>>>(p_hb, W2, p_hw);
    agg32_kernel<0><<<NB_W, TB>>>(p_hw, b2, p_h0);
    // L3: 32 -> 32, lrelu(t)+t
    gemm_kernel<32, 32, 32><<<NB_N, TB>>>(p_h0, W3, p_hw);
    agg32_kernel<1><<<NB_W, TB>>>(p_hw, b3, p_hb);
    // L4: 32 -> 32, lrelu(t)+t
    gemm_kernel<32, 32, 32><<<NB_N, TB>>>(p_hb, W4, p_hw);
    agg32_kernel<1><<<NB_W, TB>>>(p_hw, b4, p_h0);
    // L5: 32 -> 1, lrelu  (v stored in p_hb[0..NN))
    gemm5_kernel<<<NB_N, TB>>>(p_h0, W5, p_hw);
    agg5_kernel<<<NB_W, TB>>>(p_hw, b5, p_hb);

    // FC head
    fc1_kernel<<<128, 128>>>(p_hb, Wf1);
    fc2_kernel<<<1, 128>>>(bf1, Wf2, bf2, out);

    (void)in_sizes; (void)n_in; (void)out_size;
}

// round 3
// speedup vs baseline: 1.1591x; 1.1591x over previous
#include <cuda_runtime.h>
#include <cstdint>

// Problem constants (fixed by reference_code)
#define NN     38333
#define EE     (38333 * 32)          // 1226656
#define VOCAB  39816
#define EMBD   62
#define SLOPE  0.01f

// ---------------- device scratch (static allocation only) ----------------
__device__ int   g_row[EE];
__device__ int   g_col[EE];
__device__ int   g_cnt[NN];
__device__ int   g_cursor[NN];
__device__ int   g_start[NN + 1];
__device__ float g_dinv[NN];
__device__ __align__(16) float2 g_sedge[EE];      // (row-as-bits, norm)
__device__ __align__(16) float  g_h0[(size_t)NN * 128];
__device__ __align__(16) float  g_hw[(size_t)NN * 64];
__device__ __align__(16) float  g_hb[(size_t)NN * 64];
__device__ float g_fcpart[128];
__device__ int   g_okf, g_ok64;     // dtype detection flags

// ---------------- setup ----------------
__global__ void setup_kernel() {
    int i = blockIdx.x * blockDim.x + threadIdx.x;
    if (i < NN) { g_cnt[i] = 0; g_cursor[i] = 0; }
    if (i < 128) g_fcpart[i] = 0.f;
    if (i == 0) { g_okf = 1; g_ok64 = 1; }
}

// Detect edge_index dtype by sampling. See round-2 notes: float32 data reads
// back as exact small integers; int32 read as int64 packs two ids -> huge;
// int64 read as float gives denormals.
__global__ void detect_kernel(const void* eidx) {
    int t = blockIdx.x * blockDim.x + threadIdx.x;   // 4096 threads
    const float* pf = (const float*)eidx;
    float f = pf[(size_t)t * 299];
    if (!(f >= 0.f && f < (float)NN && f == floorf(f))) atomicExch(&g_okf, 0);
    const long long* p8 = (const long long*)eidx;
    long long v = p8[(size_t)t * 299];
    if (v < 0 || v >= NN) atomicExch(&g_ok64, 0);
}

__global__ void convert_hist_kernel(const void* eidx) {
    int e = blockIdx.x * blockDim.x + threadIdx.x;
    if (e >= EE) return;
    int dt = g_okf ? 2 : (g_ok64 ? 1 : 0);
    int row, col;
    if (dt == 1) {
        const long long* p = (const long long*)eidx;
        row = (int)p[e]; col = (int)p[EE + e];
    } else if (dt == 0) {
        const int* p = (const int*)eidx;
        row = p[e]; col = p[EE + e];
    } else {
        const float* p = (const float*)eidx;
        row = (int)p[e]; col = (int)p[EE + e];
    }
    g_row[e] = row; g_col[e] = col;
    atomicAdd(&g_cnt[col], 1);
}

// single-block scan of g_cnt -> g_start (exclusive), plus dinv
__global__ void scan_kernel() {
    __shared__ int sm[1024];
    int t = threadIdx.x;
    const int CH = (NN + 1023) / 1024;               // 38
    int base = t * CH;
    int s = 0;
    for (int j = 0; j < CH; j++) { int idx = base + j; if (idx < NN) s += g_cnt[idx]; }
    sm[t] = s;
    __syncthreads();
    for (int off = 1; off < 1024; off <<= 1) {
        int v = (t >= off) ? sm[t - off] : 0;
        __syncthreads();
        sm[t] += v;
        __syncthreads();
    }
    int run = sm[t] - s;                             // exclusive offset
    for (int j = 0; j < CH; j++) {
        int idx = base + j;
        if (idx < NN) { g_start[idx] = run; run += g_cnt[idx]; }
    }
    if (t == 1023) g_start[NN] = sm[1023];
    // fused dinv
    for (int i = t; i < NN; i += 1024) g_dinv[i] = rsqrtf((float)g_cnt[i] + 1.0f);
}

__global__ void scatter_kernel() {
    int e = blockIdx.x * blockDim.x + threadIdx.x;
    if (e >= EE) return;
    int col = g_col[e];
    int row = g_row[e];
    int pos = g_start[col] + atomicAdd(&g_cursor[col], 1);
    g_sedge[pos] = make_float2(__int_as_float(row), g_dinv[row] * g_dinv[col]);
}

// ---------------- feature build (independent of edges -> side stream) ----------------
__global__ void build_h0_kernel(const float* __restrict__ x, const float* __restrict__ emb) {
    int gw = (blockIdx.x * blockDim.x + threadIdx.x) >> 5;
    int lane = threadIdx.x & 31;
    if (gw >= NN) return;
    int i = gw;
    int id0 = (int)x[(size_t)i * 5 + 0];
    int id1 = (int)x[(size_t)i * 5 + 1];
    float* hr = g_h0 + (size_t)i * 128;
    for (int j = lane; j < EMBD; j += 32) {
        hr[j]        = emb[(size_t)id0 * EMBD + j];
        hr[EMBD + j] = emb[(size_t)id1 * EMBD + j];
    }
    if (lane < 3)  hr[124 + lane] = x[(size_t)i * 5 + 2 + lane];
    if (lane == 3) hr[127] = 0.f;
}

// ---------------- GEMM1: hw1 = h0 @ W1 (thread per row, W in smem broadcast) -------------
__global__ void gemm1_kernel(const float* __restrict__ h, const float* __restrict__ W,
                             float* __restrict__ hw) {
    __shared__ float Ws[128 * 64];
    for (int idx = threadIdx.x; idx < 128 * 64; idx += blockDim.x)
        Ws[idx] = (idx < 127 * 64) ? W[idx] : 0.f;
    __syncthreads();
    int row = blockIdx.x * blockDim.x + threadIdx.x;
    if (row >= NN) return;
    float acc[64];
#pragma unroll
    for (int j = 0; j < 64; j++) acc[j] = 0.f;
    const float* hr = h + (size_t)row * 128;
    for (int k = 0; k < 128; k += 4) {
        float4 hv = *reinterpret_cast<const float4*>(hr + k);
#pragma unroll
        for (int kk = 0; kk < 4; kk++) {
            float hx = (kk == 0) ? hv.x : (kk == 1) ? hv.y : (kk == 2) ? hv.z : hv.w;
#pragma unroll
            for (int j = 0; j < 64; j += 4) {
                float4 w = *reinterpret_cast<const float4*>(&Ws[(k + kk) * 64 + j]);
                acc[j]     += hx * w.x;
                acc[j + 1] += hx * w.y;
                acc[j + 2] += hx * w.z;
                acc[j + 3] += hx * w.w;
            }
        }
    }
    float* o = hw + (size_t)row * 64;
#pragma unroll
    for (int j = 0; j < 64; j += 4)
        *reinterpret_cast<float4*>(o + j) = make_float4(acc[j], acc[j + 1], acc[j + 2], acc[j + 3]);
}

__device__ __forceinline__ float act_apply(float t, int ACT) {
    float l = (t >= 0.f) ? t : SLOPE * t;
    return (ACT == 1) ? (l + t) : l;
}

// ---------------- fused agg64 + gemm(64->32): h = act(agg(hw1)+b1); out = h@W2 ------------
__global__ void aggA_kernel(const float* __restrict__ hw, const float* __restrict__ b,
                            const float* __restrict__ W2, float* __restrict__ out) {
    __shared__ float W2s[64 * 32];                  // 8KB
    __shared__ float hsm[8][64];                    // 2KB
    for (int idx = threadIdx.x; idx < 64 * 32; idx += blockDim.x) W2s[idx] = W2[idx];
    __syncthreads();
    int w = threadIdx.x >> 5;
    int gw = (blockIdx.x * blockDim.x + threadIdx.x) >> 5;
    int lane = threadIdx.x & 31;
    if (gw >= NN) return;
    int i = gw;
    float2 acc = make_float2(0.f, 0.f);
    int s = g_start[i], e2 = g_start[i + 1];
    for (int e = s; e < e2; e++) {
        float2 rn = g_sedge[e];
        int row = __float_as_int(rn.x);
        float2 hv = *reinterpret_cast<const float2*>(&hw[(size_t)row * 64 + 2 * lane]);
        acc.x += hv.x * rn.y;
        acc.y += hv.y * rn.y;
    }
    float dv = g_dinv[i];
    float sn = dv * dv;
    float2 hs = *reinterpret_cast<const float2*>(&hw[(size_t)i * 64 + 2 * lane]);
    float hx = act_apply(acc.x + hs.x * sn + b[2 * lane], 0);
    float hy = act_apply(acc.y + hs.y * sn + b[2 * lane + 1], 0);
    hsm[w][2 * lane] = hx;
    hsm[w][2 * lane + 1] = hy;
    __syncwarp();
    float o = 0.f;
#pragma unroll
    for (int k = 0; k < 64; k++) o += hsm[w][k] * W2s[k * 32 + lane];
    out[(size_t)i * 32 + lane] = o;
}

// ---------------- fused agg32 + gemm(32->32) ----------------
template <int ACT>
__global__ void aggB_kernel(const float* __restrict__ hw, const float* __restrict__ b,
                            const float* __restrict__ Wn, float* __restrict__ out) {
    __shared__ float Ws[32 * 32];                   // 4KB
    for (int idx = threadIdx.x; idx < 32 * 32; idx += blockDim.x) Ws[idx] = Wn[idx];
    __syncthreads();
    int gw = (blockIdx.x * blockDim.x + threadIdx.x) >> 5;
    int lane = threadIdx.x & 31;
    if (gw >= NN) return;
    int i = gw;
    float acc = 0.f;
    int s = g_start[i], e2 = g_start[i + 1];
    for (int e = s; e < e2; e++) {
        float2 rn = g_sedge[e];
        int row = __float_as_int(rn.x);
        acc += hw[(size_t)row * 32 + lane] * rn.y;
    }
    float dv = g_dinv[i];
    float h = act_apply(acc + hw[(size_t)i * 32 + lane] * (dv * dv) + b[lane], ACT);
    float o = 0.f;
#pragma unroll
    for (int k = 0; k < 32; k++)
        o += __shfl_sync(0xFFFFFFFFu, h, k) * Ws[k * 32 + lane];
    out[(size_t)i * 32 + lane] = o;
}

// ---------------- fused agg32 + gemm(32->1): s5[i] = act1(agg)+... dot W5 -----------------
__global__ void aggD_kernel(const float* __restrict__ hw, const float* __restrict__ b,
                            const float* __restrict__ W5, float* __restrict__ s5) {
    int gw = (blockIdx.x * blockDim.x + threadIdx.x) >> 5;
    int lane = threadIdx.x & 31;
    if (gw >= NN) return;
    int i = gw;
    float acc = 0.f;
    int s = g_start[i], e2 = g_start[i + 1];
    for (int e = s; e < e2; e++) {
        float2 rn = g_sedge[e];
        int row = __float_as_int(rn.x);
        acc += hw[(size_t)row * 32 + lane] * rn.y;
    }
    float dv = g_dinv[i];
    float h = act_apply(acc + hw[(size_t)i * 32 + lane] * (dv * dv) + b[lane], 1);
    float o = h * W5[lane];
#pragma unroll
    for (int m = 16; m > 0; m >>= 1) o += __shfl_xor_sync(0xFFFFFFFFu, o, m);
    if (lane == 0) s5[i] = o;
}

// ---------------- layer-5 aggregation -> v ----------------
__global__ void agg5_kernel(const float* __restrict__ s5, const float* __restrict__ b5,
                            float* __restrict__ v) {
    int gw = (blockIdx.x * blockDim.x + threadIdx.x) >> 5;
    int lane = threadIdx.x & 31;
    if (gw >= NN) return;
    int i = gw;
    float a = 0.f;
    int s = g_start[i], e2 = g_start[i + 1];
    for (int e = s + lane; e < e2; e += 32) {
        float2 rn = g_sedge[e];
        a += s5[__float_as_int(rn.x)] * rn.y;
    }
#pragma unroll
    for (int m = 16; m > 0; m >>= 1) a += __shfl_xor_sync(0xFFFFFFFFu, a, m);
    if (lane == 0) {
        float dv = g_dinv[i];
        float t = a + s5[i] * (dv * dv) + b5[0];
        v[i] = (t >= 0.f) ? t : SLOPE * t;
    }
}

// ---------------- final FC ----------------
__global__ void fc1_kernel(const float* __restrict__ v, const float* __restrict__ Wf1) {
    int j = threadIdx.x;           // 128
    int b = blockIdx.x;            // 512
    const int RP = (NN + 511) / 512;               // 75
    int r0 = b * RP;
    int r1 = (r0 + RP < NN) ? (r0 + RP) : NN;
    float acc = 0.f;
    for (int r = r0; r < r1; r++) acc += v[r] * Wf1[(size_t)r * 128 + j];
    atomicAdd(&g_fcpart[j], acc);
}

__global__ void fc2_kernel(const float* __restrict__ bf1, const float* __restrict__ Wf2,
                           const float* __restrict__ bf2, float* __restrict__ out) {
    __shared__ float o1[128];
    int j = threadIdx.x;
    float t = g_fcpart[j] + bf1[j];
    o1[j] = (t > 0.f) ? t : 0.f;
    __syncthreads();
    float acc = bf2[j];
    for (int k = 0; k < 128; k++) acc += o1[k] * Wf2[(size_t)k * 128 + j];
    out[j] = (acc > 0.f) ? acc : 0.f;
}

// ---------------- launcher ----------------
extern "C" void kernel_launch(void* const* d_in, const int* in_sizes, int n_in,
                              void* d_out, int out_size) {
    const float* x    = (const float*)d_in[0];
    const void*  eix  = d_in[1];
    const float* emb  = (const float*)d_in[2];
    const float* W1   = (const float*)d_in[3];
    const float* b1   = (const float*)d_in[4];
    const float* W2   = (const float*)d_in[5];
    const float* b2   = (const float*)d_in[6];
    const float* W3   = (const float*)d_in[7];
    const float* b3   = (const float*)d_in[8];
    const float* W4   = (const float*)d_in[9];
    const float* b4   = (const float*)d_in[10];
    const float* W5   = (const float*)d_in[11];
    const float* b5   = (const float*)d_in[12];
    const float* Wf1  = (const float*)d_in[13];
    const float* bf1  = (const float*)d_in[14];
    const float* Wf2  = (const float*)d_in[15];
    const float* bf2  = (const float*)d_in[16];
    float* out = (float*)d_out;

    // Resolve device addresses of scratch symbols (round-2 lesson: passing the
    // symbol from host code passes the ATS-dereferenceable host shadow).
    float *p_h0 = nullptr, *p_hw = nullptr, *p_hb = nullptr;
    cudaGetSymbolAddress((void**)&p_h0, g_h0);
    cudaGetSymbolAddress((void**)&p_hw, g_hw);
    cudaGetSymbolAddress((void**)&p_hb, g_hb);

    const int TB = 256;
    const int NB_N  = (NN + TB - 1) / TB;           // thread-per-node grids
    const int NB_E  = (EE + TB - 1) / TB;           // thread-per-edge grids
    const int NB_W  = (NN + 7) / 8;                 // warp-per-node grids (8 warps/block)

    // Side stream: build_h0 + gemm1 are independent of the edge pipeline.
    // Event fork/join off the (captured) legacy default stream.
    cudaStream_t s2;
    cudaStreamCreateWithFlags(&s2, cudaStreamNonBlocking);
    cudaEvent_t evFork, evJoin;
    cudaEventCreateWithFlags(&evFork, cudaEventDisableTiming);
    cudaEventCreateWithFlags(&evJoin, cudaEventDisableTiming);

    cudaEventRecord(evFork, 0);
    cudaStreamWaitEvent(s2, evFork, 0);
    build_h0_kernel<<<NB_W, TB, 0, s2>>>(x, emb);
    gemm1_kernel<<<NB_N, TB, 0, s2>>>(p_h0, W1, p_hw);          // hw1 (64) -> g_hw
    cudaEventRecord(evJoin, s2);

    // Main stream: edge preprocessing
    setup_kernel<<<NB_N, TB>>>();
    detect_kernel<<<16, 256>>>(eix);
    convert_hist_kernel<<<NB_E, TB>>>(eix);
    scan_kernel<<<1, 1024>>>();
    scatter_kernel<<<NB_E, TB>>>();

    cudaStreamWaitEvent(0, evJoin, 0);                          // join before agg

    // Fused layer chain
    aggA_kernel<<<NB_W, TB>>>(p_hw, b1, W2, p_hb);              // hw2 (32) -> g_hb
    aggB_kernel<0><<<NB_W, TB>>>(p_hb, b2, W3, p_h0);           // hw3 -> g_h0
    aggB_kernel<1><<<NB_W, TB>>>(p_h0, b3, W4, p_hb);           // hw4 -> g_hb
    aggD_kernel<<<NB_W, TB>>>(p_hb, b4, W5, p_hw);              // s5  -> g_hw
    agg5_kernel<<<NB_W, TB>>>(p_hw, b5, p_h0);                  // v   -> g_h0

    // FC head
    fc1_kernel<<<512, 128>>>(p_h0, Wf1);
    fc2_kernel<<<1, 128>>>(bf1, Wf2, bf2, out);

    (void)in_sizes; (void)n_in; (void)out_size;
}

// round 4
// speedup vs baseline: 1.2513x; 1.0795x over previous
#include <cuda_runtime.h>
#include <cuda_fp16.h>
#include <cstdint>

// Problem constants (fixed by reference_code)
#define NN     38333
#define EE     (38333 * 32)          // 1226656
#define VOCAB  39816
#define EMBD   62
#define SLOPE  0.01f

// ---------------- device scratch (static allocation only) ----------------
__device__ int    g_cnt[NN];
__device__ int    g_cursor[NN];
__device__ int    g_start[NN + 1];
__device__ float  g_dinv[NN];
__device__ int    g_erow[EE];                       // sorted-by-col edge sources
__device__ __align__(16) float   g_h0[(size_t)NN * 128];
__device__ __align__(16) float   g_hw[(size_t)NN * 64];   // gemm1 out fp32
__device__ __align__(8)  __half2 g_f64[(size_t)NN * 32];  // prescaled hw1, fp16 (64 feats)
__device__ __align__(4)  __half  g_fa[(size_t)NN * 32];   // prescaled 32-wide ping
__device__ __align__(4)  __half  g_fb[(size_t)NN * 32];   // prescaled 32-wide pong
__device__ float  g_s5[NN];                         // prescaled layer-5 scalar
__device__ float  g_v[NN];
__device__ float  g_fcpart[128];
// dtype detection "bad" flags: zero-initialized at module load; reset to 0 by
// fc2 at the end of every replay, so no init kernel / no same-grid race.
__device__ int    g_badf;      // 1 => NOT float32
__device__ int    g_bad64;     // 1 => NOT int64

__device__ __forceinline__ int edge_dtype() {      // 2=float,1=int64,0=int32
    return (!g_badf) ? 2 : ((!g_bad64) ? 1 : 0);
}

// ---------------- setup + dtype detect (fused) ----------------
__global__ void setup_kernel(const void* eidx) {
    int i = blockIdx.x * blockDim.x + threadIdx.x;
    if (i < NN) { g_cnt[i] = 0; g_cursor[i] = 0; }
    if (i < 128) g_fcpart[i] = 0.f;
    if (i < 4096) {
        const float* pf = (const float*)eidx;
        float f = pf[(size_t)i * 299];
        if (!(f >= 0.f && f < (float)NN && f == floorf(f))) atomicOr(&g_badf, 1);
        const long long* p8 = (const long long*)eidx;
        long long v = p8[(size_t)i * 299];
        if (v < 0 || v >= NN) atomicOr(&g_bad64, 1);
    }
}

// histogram of destination (col) only
__global__ void convert_hist_kernel(const void* eidx) {
    int e = blockIdx.x * blockDim.x + threadIdx.x;
    if (e >= EE) return;
    int dt = edge_dtype();
    int col;
    if (dt == 1)      col = (int)((const long long*)eidx)[EE + e];
    else if (dt == 0) col = ((const int*)eidx)[EE + e];
    else              col = (int)((const float*)eidx)[EE + e];
    atomicAdd(&g_cnt[col], 1);
}

// single-block scan of g_cnt -> g_start (exclusive), plus dinv
__global__ void scan_kernel() {
    __shared__ int sm[1024];
    int t = threadIdx.x;
    const int CH = (NN + 1023) / 1024;               // 38
    int base = t * CH;
    int s = 0;
    for (int j = 0; j < CH; j++) { int idx = base + j; if (idx < NN) s += g_cnt[idx]; }
    sm[t] = s;
    __syncthreads();
    for (int off = 1; off < 1024; off <<= 1) {
        int v = (t >= off) ? sm[t - off] : 0;
        __syncthreads();
        sm[t] += v;
        __syncthreads();
    }
    int run = sm[t] - s;                             // exclusive offset
    for (int j = 0; j < CH; j++) {
        int idx = base + j;
        if (idx < NN) { g_start[idx] = run; run += g_cnt[idx]; }
    }
    if (t == 1023) g_start[NN] = sm[1023];
    for (int i = t; i < NN; i += 1024) g_dinv[i] = rsqrtf((float)g_cnt[i] + 1.0f);
}

// bucket-scatter sorted row index (4B per edge, no norm needed anymore)
__global__ void scatter_kernel(const void* eidx) {
    int e = blockIdx.x * blockDim.x + threadIdx.x;
    if (e >= EE) return;
    int dt = edge_dtype();
    int row, col;
    if (dt == 1) {
        const long long* p = (const long long*)eidx;
        row = (int)p[e]; col = (int)p[EE + e];
    } else if (dt == 0) {
        const int* p = (const int*)eidx;
        row = p[e]; col = p[EE + e];
    } else {
        const float* p = (const float*)eidx;
        row = (int)p[e]; col = (int)p[EE + e];
    }
    int pos = g_start[col] + atomicAdd(&g_cursor[col], 1);
    g_erow[pos] = row;
}

// ---------------- feature build (side stream) ----------------
__global__ void build_h0_kernel(const float* __restrict__ x, const float* __restrict__ emb) {
    int gw = (blockIdx.x * blockDim.x + threadIdx.x) >> 5;
    int lane = threadIdx.x & 31;
    if (gw >= NN) return;
    int i = gw;
    int id0 = (int)x[(size_t)i * 5 + 0];
    int id1 = (int)x[(size_t)i * 5 + 1];
    float* hr = g_h0 + (size_t)i * 128;
    for (int j = lane; j < EMBD; j += 32) {
        hr[j]        = emb[(size_t)id0 * EMBD + j];
        hr[EMBD + j] = emb[(size_t)id1 * EMBD + j];
    }
    if (lane < 3)  hr[124 + lane] = x[(size_t)i * 5 + 2 + lane];
    if (lane == 3) hr[127] = 0.f;
}

// ---------------- GEMM1: hw1 = h0 @ W1 ----------------
__global__ void gemm1_kernel(const float* __restrict__ W) {
    __shared__ float Ws[128 * 64];
    for (int idx = threadIdx.x; idx < 128 * 64; idx += blockDim.x)
        Ws[idx] = (idx < 127 * 64) ? W[idx] : 0.f;
    __syncthreads();
    int row = blockIdx.x * blockDim.x + threadIdx.x;
    if (row >= NN) return;
    float acc[64];
#pragma unroll
    for (int j = 0; j < 64; j++) acc[j] = 0.f;
    const float* hr = g_h0 + (size_t)row * 128;
    for (int k = 0; k < 128; k += 4) {
        float4 hv = *reinterpret_cast<const float4*>(hr + k);
#pragma unroll
        for (int kk = 0; kk < 4; kk++) {
            float hx = (kk == 0) ? hv.x : (kk == 1) ? hv.y : (kk == 2) ? hv.z : hv.w;
#pragma unroll
            for (int j = 0; j < 64; j += 4) {
                float4 w = *reinterpret_cast<const float4*>(&Ws[(k + kk) * 64 + j]);
                acc[j]     += hx * w.x;
                acc[j + 1] += hx * w.y;
                acc[j + 2] += hx * w.z;
                acc[j + 3] += hx * w.w;
            }
        }
    }
    float* o = g_hw + (size_t)row * 64;
#pragma unroll
    for (int j = 0; j < 64; j += 4)
        *reinterpret_cast<float4*>(o + j) = make_float4(acc[j], acc[j + 1], acc[j + 2], acc[j + 3]);
}

// prescale hw1 by dinv and convert to fp16 (needs scan done; overlaps scatter)
__global__ void prescale_kernel() {
    int t = blockIdx.x * blockDim.x + threadIdx.x;     // NN*32 threads
    if (t >= NN * 32) return;
    int i = t >> 5, j = t & 31;
    float d = g_dinv[i];
    float2 v = *reinterpret_cast<const float2*>(&g_hw[(size_t)i * 64 + 2 * j]);
    g_f64[(size_t)i * 32 + j] = __floats2half2_rn(d * v.x, d * v.y);
}

__device__ __forceinline__ float act_apply(float t, int ACT) {
    float l = (t >= 0.f) ? t : SLOPE * t;
    return (ACT == 1) ? (l + t) : l;
}

// ---------------- fused: agg(64,fp16) -> lrelu -> @W2 -> prescale fp16 out ---------------
__global__ void aggA_kernel(const float* __restrict__ b, const float* __restrict__ W2) {
    __shared__ float W2s[64 * 32];                  // 8KB
    __shared__ float hsm[8][64];                    // 2KB
    for (int idx = threadIdx.x; idx < 64 * 32; idx += blockDim.x) W2s[idx] = W2[idx];
    __syncthreads();
    int w = threadIdx.x >> 5;
    int gw = (blockIdx.x * blockDim.x + threadIdx.x) >> 5;
    int lane = threadIdx.x & 31;
    if (gw >= NN) return;
    int i = gw;
    float accx = 0.f, accy = 0.f;
    int s = g_start[i], e2 = g_start[i + 1];
#pragma unroll 4
    for (int e = s; e < e2; e++) {
        int row = g_erow[e];
        float2 f = __half22float2(g_f64[(size_t)row * 32 + lane]);
        accx += f.x; accy += f.y;
    }
    float2 fi = __half22float2(g_f64[(size_t)i * 32 + lane]);
    float d = g_dinv[i];
    float hx = act_apply(d * (accx + fi.x) + b[2 * lane], 0);
    float hy = act_apply(d * (accy + fi.y) + b[2 * lane + 1], 0);
    hsm[w][2 * lane] = hx;
    hsm[w][2 * lane + 1] = hy;
    __syncwarp();
    float o = 0.f;
#pragma unroll
    for (int k = 0; k < 64; k++) o += hsm[w][k] * W2s[k * 32 + lane];
    g_fa[(size_t)i * 32 + lane] = __float2half_rn(d * o);
}

// ---------------- fused: agg(32,fp16) -> act -> @W -> prescale fp16 out ------------------
template <int ACT>
__global__ void aggB_kernel(const __half* __restrict__ in, const float* __restrict__ b,
                            const float* __restrict__ Wn, __half* __restrict__ out) {
    __shared__ float Ws[32 * 32];                   // 4KB
    __shared__ float hsm[8][32];                    // 1KB
    for (int idx = threadIdx.x; idx < 32 * 32; idx += blockDim.x) Ws[idx] = Wn[idx];
    __syncthreads();
    int w = threadIdx.x >> 5;
    int gw = (blockIdx.x * blockDim.x + threadIdx.x) >> 5;
    int lane = threadIdx.x & 31;
    if (gw >= NN) return;
    int i = gw;
    float acc = 0.f;
    int s = g_start[i], e2 = g_start[i + 1];
#pragma unroll 4
    for (int e = s; e < e2; e++) {
        int row = g_erow[e];
        acc += __half2float(in[(size_t)row * 32 + lane]);
    }
    acc += __half2float(in[(size_t)i * 32 + lane]);
    float d = g_dinv[i];
    float h = act_apply(d * acc + b[lane], ACT);
    hsm[w][lane] = h;
    __syncwarp();
    float o = 0.f;
#pragma unroll
    for (int k = 0; k < 32; k++) o += hsm[w][k] * Ws[k * 32 + lane];
    out[(size_t)i * 32 + lane] = __float2half_rn(d * o);
}

// ---------------- fused: agg(32,fp16) -> lrelu+id -> dot W5 -> prescaled scalar ----------
__global__ void aggD_kernel(const __half* __restrict__ in, const float* __restrict__ b,
                            const float* __restrict__ W5) {
    int gw = (blockIdx.x * blockDim.x + threadIdx.x) >> 5;
    int lane = threadIdx.x & 31;
    if (gw >= NN) return;
    int i = gw;
    float acc = 0.f;
    int s = g_start[i], e2 = g_start[i + 1];
#pragma unroll 4
    for (int e = s; e < e2; e++) {
        int row = g_erow[e];
        acc += __half2float(in[(size_t)row * 32 + lane]);
    }
    acc += __half2float(in[(size_t)i * 32 + lane]);
    float d = g_dinv[i];
    float h = act_apply(d * acc + b[lane], 1);
    float o = h * W5[lane];
#pragma unroll
    for (int m = 16; m > 0; m >>= 1) o += __shfl_xor_sync(0xFFFFFFFFu, o, m);
    if (lane == 0) g_s5[i] = d * o;                 // prescaled
}

// ---------------- layer-5 aggregation -> v ----------------
__global__ void agg5_kernel(const float* __restrict__ b5) {
    int gw = (blockIdx.x * blockDim.x + threadIdx.x) >> 5;
    int lane = threadIdx.x & 31;
    if (gw >= NN) return;
    int i = gw;
    float a = 0.f;
    int s = g_start[i], e2 = g_start[i + 1];
    for (int e = s + lane; e < e2; e += 32) a += g_s5[g_erow[e]];
#pragma unroll
    for (int m = 16; m > 0; m >>= 1) a += __shfl_xor_sync(0xFFFFFFFFu, a, m);
    if (lane == 0) {
        float t = g_dinv[i] * (a + g_s5[i]) + b5[0];
        g_v[i] = (t >= 0.f) ? t : SLOPE * t;
    }
}

// ---------------- final FC ----------------
__global__ void fc1_kernel(const float* __restrict__ Wf1) {
    int j = threadIdx.x;           // 128
    int b = blockIdx.x;            // 512
    const int RP = (NN + 511) / 512;               // 75
    int r0 = b * RP;
    int r1 = (r0 + RP < NN) ? (r0 + RP) : NN;
    float acc = 0.f;
    for (int r = r0; r < r1; r++) acc += g_v[r] * Wf1[(size_t)r * 128 + j];
    atomicAdd(&g_fcpart[j], acc);
}

__global__ void fc2_kernel(const float* __restrict__ bf1, const float* __restrict__ Wf2,
                           const float* __restrict__ bf2, float* __restrict__ out) {
    __shared__ float o1[128];
    int j = threadIdx.x;
    float t = g_fcpart[j] + bf1[j];
    o1[j] = (t > 0.f) ? t : 0.f;
    __syncthreads();
    float acc = bf2[j];
    for (int k = 0; k < 128; k++) acc += o1[k] * Wf2[(size_t)k * 128 + j];
    out[j] = (acc > 0.f) ? acc : 0.f;
    if (j == 0) { g_badf = 0; g_bad64 = 0; }        // reset detect flags for next replay
}

// ---------------- launcher ----------------
extern "C" void kernel_launch(void* const* d_in, const int* in_sizes, int n_in,
                              void* d_out, int out_size) {
    const float* x    = (const float*)d_in[0];
    const void*  eix  = d_in[1];
    const float* emb  = (const float*)d_in[2];
    const float* W1   = (const float*)d_in[3];
    const float* b1   = (const float*)d_in[4];
    const float* W2   = (const float*)d_in[5];
    const float* b2   = (const float*)d_in[6];
    const float* W3   = (const float*)d_in[7];
    const float* b3   = (const float*)d_in[8];
    const float* W4   = (const float*)d_in[9];
    const float* b4   = (const float*)d_in[10];
    const float* W5   = (const float*)d_in[11];
    const float* b5   = (const float*)d_in[12];
    const float* Wf1  = (const float*)d_in[13];
    const float* bf1  = (const float*)d_in[14];
    const float* Wf2  = (const float*)d_in[15];
    const float* bf2  = (const float*)d_in[16];
    float* out = (float*)d_out;

    // Resolve device addresses for ping-pong buffers passed as params
    // (round-2 lesson: never pass a __device__ symbol from host code directly).
    __half *p_fa = nullptr, *p_fb = nullptr;
    cudaGetSymbolAddress((void**)&p_fa, g_fa);
    cudaGetSymbolAddress((void**)&p_fb, g_fb);

    const int TB = 256;
    const int NB_N = (NN + TB - 1) / TB;             // 150
    const int NB_E = (EE + TB - 1) / TB;             // 4792
    const int NB_W = (NN + 7) / 8;                   // 4792 (warp per node)
    const int NB_P = (NN * 32 + TB - 1) / TB;        // prescale

    cudaStream_t s2;
    cudaStreamCreateWithFlags(&s2, cudaStreamNonBlocking);
    cudaEvent_t evFork, evScan, evPre;
    cudaEventCreateWithFlags(&evFork, cudaEventDisableTiming);
    cudaEventCreateWithFlags(&evScan, cudaEventDisableTiming);
    cudaEventCreateWithFlags(&evPre,  cudaEventDisableTiming);

    // fork side stream: h0 build + gemm1 (edge-independent)
    cudaEventRecord(evFork, 0);
    cudaStreamWaitEvent(s2, evFork, 0);
    build_h0_kernel<<<NB_W, TB, 0, s2>>>(x, emb);
    gemm1_kernel<<<NB_N, TB, 0, s2>>>(W1);

    // main: edge preprocessing
    setup_kernel<<<NB_N, TB>>>(eix);
    convert_hist_kernel<<<NB_E, TB>>>(eix);
    scan_kernel<<<1, 1024>>>();
    cudaEventRecord(evScan, 0);
    // side: prescale needs gemm1 (same stream) + scan (event); overlaps scatter
    cudaStreamWaitEvent(s2, evScan, 0);
    prescale_kernel<<<NB_P, TB, 0, s2>>>();
    cudaEventRecord(evPre, s2);
    // main continues
    scatter_kernel<<<NB_E, TB>>>(eix);
    cudaStreamWaitEvent(0, evPre, 0);

    // fused GCN chain
    aggA_kernel<<<NB_W, TB>>>(b1, W2);               // -> g_fa (hw2')
    aggB_kernel<0><<<NB_W, TB>>>(p_fa, b2, W3, p_fb);// -> g_fb (hw3')
    aggB_kernel<1><<<NB_W, TB>>>(p_fb, b3, W4, p_fa);// -> g_fa (hw4')
    aggD_kernel<<<NB_W, TB>>>(p_fa, b4, W5);         // -> g_s5
    agg5_kernel<<<NB_W, TB>>>(b5);                   // -> g_v

    // FC head
    fc1_kernel<<<512, 128>>>(Wf1);
    fc2_kernel<<<1, 128>>>(bf1, Wf2, bf2, out);

    (void)in_sizes; (void)n_in; (void)out_size;
}

// round 5
// speedup vs baseline: 1.3494x; 1.0785x over previous
#include <cuda_runtime.h>
#include <cuda_fp16.h>
#include <cstdint>

// Problem constants (fixed by reference_code)
#define NN     38333
#define EE     (38333 * 32)          // 1226656 (divisible by 4)
#define VOCAB  39816
#define EMBD   62
#define SLOPE  0.01f
#define SCB    ((NN + 255) / 256)    // 150 scan blocks

// ---------------- device scratch (static allocation only) ----------------
// Invariant: g_cnt / g_cursor are all-zero at kernel_launch entry (zero-init at
// module load; re-zeroed by cleanup_kernel each replay). g_fcpart re-zeroed by fc2.
__device__ int    g_cnt[NN];
__device__ int    g_cursor[NN];
__device__ int    g_part[256];
__device__ int    g_start[NN + 1];
__device__ float  g_dinv[NN];
__device__ int    g_erow[EE];                       // sorted-by-col edge sources
__device__ __align__(16) float   g_h0[(size_t)NN * 128];
__device__ __align__(16) float   g_hw[(size_t)NN * 64];   // gemm1 out fp32
__device__ __align__(8)  __half2 g_f64[(size_t)NN * 32];  // prescaled hw1, fp16
__device__ __align__(4)  __half  g_fa[(size_t)NN * 32];   // prescaled ping
__device__ __align__(4)  __half  g_fb[(size_t)NN * 32];   // prescaled pong
__device__ float  g_s5[NN];
__device__ float  g_v[NN];
__device__ float  g_fcpart[128];

// Stateless dtype probe: 4 fixed sample points, uniform across all threads
// (L1-broadcast). float data -> exact small ints; int32 as int64 packs two ids
// (huge); int64 low word as float is a denormal (fails floor test).
__device__ __forceinline__ int edge_dtype_probe(const void* eidx) {
    bool okf = true, ok64 = true;
#pragma unroll
    for (int k = 0; k < 4; k++) {
        size_t idx = (size_t)k * 151123 + 17;            // < EE, bounds-safe all layouts
        float f = ((const float*)eidx)[idx];
        if (!(f >= 0.f && f < (float)NN && f == floorf(f))) okf = false;
        long long v = ((const long long*)eidx)[idx];
        if (v < 0 || v >= NN) ok64 = false;
    }
    return okf ? 2 : (ok64 ? 1 : 0);                     // 2=float,1=int64,0=int32
}

// ---------------- histogram of destinations (4 edges/thread, 16B loads) --------
__global__ void convert_hist_kernel(const void* eidx) {
    int q = blockIdx.x * blockDim.x + threadIdx.x;
    if (q >= EE / 4) return;
    int dt = edge_dtype_probe(eidx);
    int c[4];
    if (dt == 1) {
        const longlong2* p = (const longlong2*)((const long long*)eidx + EE);
        longlong2 a = p[2 * q], b = p[2 * q + 1];
        c[0] = (int)a.x; c[1] = (int)a.y; c[2] = (int)b.x; c[3] = (int)b.y;
    } else if (dt == 0) {
        const int4* p = (const int4*)((const int*)eidx + EE);
        int4 a = p[q]; c[0] = a.x; c[1] = a.y; c[2] = a.z; c[3] = a.w;
    } else {
        const float4* p = (const float4*)((const float*)eidx + EE);
        float4 a = p[q]; c[0] = (int)a.x; c[1] = (int)a.y; c[2] = (int)a.z; c[3] = (int)a.w;
    }
#pragma unroll
    for (int k = 0; k < 4; k++) atomicAdd(&g_cnt[c[k]], 1);
}

// ---------------- parallel 3-phase scan ----------------
__global__ void scanP1_kernel() {                    // grid SCB, block 256
    __shared__ int sm[256];
    int i = blockIdx.x * 256 + threadIdx.x;
    int v = (i < NN) ? g_cnt[i] : 0;
    sm[threadIdx.x] = v;
    __syncthreads();
    for (int off = 128; off > 0; off >>= 1) {
        if (threadIdx.x < off) sm[threadIdx.x] += sm[threadIdx.x + off];
        __syncthreads();
    }
    if (threadIdx.x == 0) g_part[blockIdx.x] = sm[0];
}

__global__ void scanP2_kernel() {                    // 1 block, 256 threads
    __shared__ int sm[256];
    int t = threadIdx.x;
    int v = (t < SCB) ? g_part[t] : 0;
    sm[t] = v;
    __syncthreads();
    for (int off = 1; off < 256; off <<= 1) {
        int u = (t >= off) ? sm[t - off] : 0;
        __syncthreads();
        sm[t] += u;
        __syncthreads();
    }
    g_part[t] = sm[t] - v;                           // exclusive
}

__global__ void scanP3_kernel() {                    // grid SCB, block 256 (+dinv)
    __shared__ int sm[256];
    int t = threadIdx.x;
    int i = blockIdx.x * 256 + t;
    int c = (i < NN) ? g_cnt[i] : 0;
    sm[t] = c;
    __syncthreads();
    for (int off = 1; off < 256; off <<= 1) {
        int u = (t >= off) ? sm[t - off] : 0;
        __syncthreads();
        sm[t] += u;
        __syncthreads();
    }
    if (i < NN) {
        g_start[i] = sm[t] - c + g_part[blockIdx.x];
        g_dinv[i] = rsqrtf((float)c + 1.0f);
    }
    if (blockIdx.x == 0 && t == 0) g_start[NN] = EE;
}

// ---------------- bucket scatter (4 edges/thread) ----------------
__global__ void scatter_kernel(const void* eidx) {
    int q = blockIdx.x * blockDim.x + threadIdx.x;
    if (q >= EE / 4) return;
    int dt = edge_dtype_probe(eidx);
    int r[4], c[4];
    if (dt == 1) {
        const longlong2* pr = (const longlong2*)eidx;
        const longlong2* pc = (const longlong2*)((const long long*)eidx + EE);
        longlong2 a = pr[2 * q], b = pr[2 * q + 1];
        r[0] = (int)a.x; r[1] = (int)a.y; r[2] = (int)b.x; r[3] = (int)b.y;
        a = pc[2 * q]; b = pc[2 * q + 1];
        c[0] = (int)a.x; c[1] = (int)a.y; c[2] = (int)b.x; c[3] = (int)b.y;
    } else if (dt == 0) {
        const int4* pr = (const int4*)eidx;
        const int4* pc = (const int4*)((const int*)eidx + EE);
        int4 a = pr[q]; r[0] = a.x; r[1] = a.y; r[2] = a.z; r[3] = a.w;
        a = pc[q];      c[0] = a.x; c[1] = a.y; c[2] = a.z; c[3] = a.w;
    } else {
        const float4* pr = (const float4*)eidx;
        const float4* pc = (const float4*)((const float*)eidx + EE);
        float4 a = pr[q]; r[0] = (int)a.x; r[1] = (int)a.y; r[2] = (int)a.z; r[3] = (int)a.w;
        a = pc[q];        c[0] = (int)a.x; c[1] = (int)a.y; c[2] = (int)a.z; c[3] = (int)a.w;
    }
#pragma unroll
    for (int k = 0; k < 4; k++) {
        int pos = g_start[c[k]] + atomicAdd(&g_cursor[c[k]], 1);
        g_erow[pos] = r[k];
    }
}

// cleanup (side stream, overlapped with agg chain): restore zero invariant
__global__ void cleanup_kernel() {
    int i = blockIdx.x * blockDim.x + threadIdx.x;
    if (i < NN) { g_cnt[i] = 0; g_cursor[i] = 0; }
}

// ---------------- feature build (side stream) ----------------
__global__ void build_h0_kernel(const float* __restrict__ x, const float* __restrict__ emb) {
    int gw = (blockIdx.x * blockDim.x + threadIdx.x) >> 5;
    int lane = threadIdx.x & 31;
    if (gw >= NN) return;
    int i = gw;
    int id0 = (int)x[(size_t)i * 5 + 0];
    int id1 = (int)x[(size_t)i * 5 + 1];
    float* hr = g_h0 + (size_t)i * 128;
    for (int j = lane; j < EMBD; j += 32) {
        hr[j]        = emb[(size_t)id0 * EMBD + j];
        hr[EMBD + j] = emb[(size_t)id1 * EMBD + j];
    }
    if (lane < 3)  hr[124 + lane] = x[(size_t)i * 5 + 2 + lane];
    if (lane == 3) hr[127] = 0.f;
}

// ---------------- GEMM1: hw1 = h0 @ W1 ----------------
__global__ void gemm1_kernel(const float* __restrict__ W) {
    __shared__ float Ws[128 * 64];
    for (int idx = threadIdx.x; idx < 128 * 64; idx += blockDim.x)
        Ws[idx] = (idx < 127 * 64) ? W[idx] : 0.f;
    __syncthreads();
    int row = blockIdx.x * blockDim.x + threadIdx.x;
    if (row >= NN) return;
    float acc[64];
#pragma unroll
    for (int j = 0; j < 64; j++) acc[j] = 0.f;
    const float* hr = g_h0 + (size_t)row * 128;
    for (int k = 0; k < 128; k += 4) {
        float4 hv = *reinterpret_cast<const float4*>(hr + k);
#pragma unroll
        for (int kk = 0; kk < 4; kk++) {
            float hx = (kk == 0) ? hv.x : (kk == 1) ? hv.y : (kk == 2) ? hv.z : hv.w;
#pragma unroll
            for (int j = 0; j < 64; j += 4) {
                float4 w = *reinterpret_cast<const float4*>(&Ws[(k + kk) * 64 + j]);
                acc[j]     += hx * w.x;
                acc[j + 1] += hx * w.y;
                acc[j + 2] += hx * w.z;
                acc[j + 3] += hx * w.w;
            }
        }
    }
    float* o = g_hw + (size_t)row * 64;
#pragma unroll
    for (int j = 0; j < 64; j += 4)
        *reinterpret_cast<float4*>(o + j) = make_float4(acc[j], acc[j + 1], acc[j + 2], acc[j + 3]);
}

// prescale hw1 by dinv -> fp16 (side stream; needs scanP3 + gemm1)
__global__ void prescale_kernel() {
    int t = blockIdx.x * blockDim.x + threadIdx.x;
    if (t >= NN * 32) return;
    int i = t >> 5, j = t & 31;
    float d = g_dinv[i];
    float2 v = *reinterpret_cast<const float2*>(&g_hw[(size_t)i * 64 + 2 * j]);
    g_f64[(size_t)i * 32 + j] = __floats2half2_rn(d * v.x, d * v.y);
}

__device__ __forceinline__ float act_apply(float t, int ACT) {
    float l = (t >= 0.f) ? t : SLOPE * t;
    return (ACT == 1) ? (l + t) : l;
}

// ---------------- fused: agg(64,fp16) -> lrelu -> @W2 -> prescaled fp16 -----------------
__global__ void aggA_kernel(const float* __restrict__ b, const float* __restrict__ W2) {
    __shared__ float W2s[64 * 32];
    __shared__ float hsm[8][64];
    for (int idx = threadIdx.x; idx < 64 * 32; idx += blockDim.x) W2s[idx] = W2[idx];
    __syncthreads();
    int w = threadIdx.x >> 5;
    int gw = (blockIdx.x * blockDim.x + threadIdx.x) >> 5;
    int lane = threadIdx.x & 31;
    if (gw >= NN) return;
    int i = gw;
    float ax0 = 0.f, ay0 = 0.f, ax1 = 0.f, ay1 = 0.f;
    int s = g_start[i], e2 = g_start[i + 1];
    int e = s;
    for (; e + 8 <= e2; e += 8) {
        int r[8];
#pragma unroll
        for (int k = 0; k < 8; k++) r[k] = g_erow[e + k];
#pragma unroll
        for (int k = 0; k < 8; k++) {
            float2 f = __half22float2(g_f64[(size_t)r[k] * 32 + lane]);
            if (k & 1) { ax1 += f.x; ay1 += f.y; } else { ax0 += f.x; ay0 += f.y; }
        }
    }
    for (; e < e2; e++) {
        float2 f = __half22float2(g_f64[(size_t)g_erow[e] * 32 + lane]);
        ax0 += f.x; ay0 += f.y;
    }
    float2 fi = __half22float2(g_f64[(size_t)i * 32 + lane]);
    float d = g_dinv[i];
    float hx = act_apply(d * (ax0 + ax1 + fi.x) + b[2 * lane], 0);
    float hy = act_apply(d * (ay0 + ay1 + fi.y) + b[2 * lane + 1], 0);
    hsm[w][2 * lane] = hx;
    hsm[w][2 * lane + 1] = hy;
    __syncwarp();
    float o = 0.f;
#pragma unroll
    for (int k = 0; k < 64; k++) o += hsm[w][k] * W2s[k * 32 + lane];
    g_fa[(size_t)i * 32 + lane] = __float2half_rn(d * o);
}

// ---------------- fused: agg(32,fp16) -> act -> @W -> prescaled fp16 --------------------
template <int ACT>
__global__ void aggB_kernel(const __half* __restrict__ in, const float* __restrict__ b,
                            const float* __restrict__ Wn, __half* __restrict__ out) {
    __shared__ float Ws[32 * 32];
    __shared__ float hsm[8][32];
    for (int idx = threadIdx.x; idx < 32 * 32; idx += blockDim.x) Ws[idx] = Wn[idx];
    __syncthreads();
    int w = threadIdx.x >> 5;
    int gw = (blockIdx.x * blockDim.x + threadIdx.x) >> 5;
    int lane = threadIdx.x & 31;
    if (gw >= NN) return;
    int i = gw;
    float a0 = 0.f, a1 = 0.f;
    int s = g_start[i], e2 = g_start[i + 1];
    int e = s;
    for (; e + 8 <= e2; e += 8) {
        int r[8];
#pragma unroll
        for (int k = 0; k < 8; k++) r[k] = g_erow[e + k];
#pragma unroll
        for (int k = 0; k < 8; k++) {
            float f = __half2float(in[(size_t)r[k] * 32 + lane]);
            if (k & 1) a1 += f; else a0 += f;
        }
    }
    for (; e < e2; e++) a0 += __half2float(in[(size_t)g_erow[e] * 32 + lane]);
    a0 += a1 + __half2float(in[(size_t)i * 32 + lane]);
    float d = g_dinv[i];
    float h = act_apply(d * a0 + b[lane], ACT);
    hsm[w][lane] = h;
    __syncwarp();
    float o = 0.f;
#pragma unroll
    for (int k = 0; k < 32; k++) o += hsm[w][k] * Ws[k * 32 + lane];
    out[(size_t)i * 32 + lane] = __float2half_rn(d * o);
}

// ---------------- fused: agg(32,fp16) -> lrelu+id -> dot W5 -> prescaled scalar ---------
__global__ void aggD_kernel(const __half* __restrict__ in, const float* __restrict__ b,
                            const float* __restrict__ W5) {
    int gw = (blockIdx.x * blockDim.x + threadIdx.x) >> 5;
    int lane = threadIdx.x & 31;
    if (gw >= NN) return;
    int i = gw;
    float a0 = 0.f, a1 = 0.f;
    int s = g_start[i], e2 = g_start[i + 1];
    int e = s;
    for (; e + 8 <= e2; e += 8) {
        int r[8];
#pragma unroll
        for (int k = 0; k < 8; k++) r[k] = g_erow[e + k];
#pragma unroll
        for (int k = 0; k < 8; k++) {
            float f = __half2float(in[(size_t)r[k] * 32 + lane]);
            if (k & 1) a1 += f; else a0 += f;
        }
    }
    for (; e < e2; e++) a0 += __half2float(in[(size_t)g_erow[e] * 32 + lane]);
    a0 += a1 + __half2float(in[(size_t)i * 32 + lane]);
    float d = g_dinv[i];
    float h = act_apply(d * a0 + b[lane], 1);
    float o = h * W5[lane];
#pragma unroll
    for (int m = 16; m > 0; m >>= 1) o += __shfl_xor_sync(0xFFFFFFFFu, o, m);
    if (lane == 0) g_s5[i] = d * o;                  // prescaled
}

// ---------------- layer-5 aggregation -> v ----------------
__global__ void agg5_kernel(const float* __restrict__ b5) {
    int gw = (blockIdx.x * blockDim.x + threadIdx.x) >> 5;
    int lane = threadIdx.x & 31;
    if (gw >= NN) return;
    int i = gw;
    float a = 0.f;
    int s = g_start[i], e2 = g_start[i + 1];
    for (int e = s + lane; e < e2; e += 32) a += g_s5[g_erow[e]];
#pragma unroll
    for (int m = 16; m > 0; m >>= 1) a += __shfl_xor_sync(0xFFFFFFFFu, a, m);
    if (lane == 0) {
        float t = g_dinv[i] * (a + g_s5[i]) + b5[0];
        g_v[i] = (t >= 0.f) ? t : SLOPE * t;
    }
}

// ---------------- final FC ----------------
__global__ void fc1_kernel(const float* __restrict__ Wf1) {
    int j = threadIdx.x;            // 128
    int b = blockIdx.x;             // 512
    const int RP = (NN + 511) / 512;
    int r0 = b * RP;
    int r1 = (r0 + RP < NN) ? (r0 + RP) : NN;
    float acc = 0.f;
#pragma unroll 4
    for (int r = r0; r < r1; r++) acc += g_v[r] * Wf1[(size_t)r * 128 + j];
    atomicAdd(&g_fcpart[j], acc);
}

__global__ void fc2_kernel(const float* __restrict__ bf1, const float* __restrict__ Wf2,
                           const float* __restrict__ bf2, float* __restrict__ out) {
    __shared__ float o1[128];
    int j = threadIdx.x;
    float t = g_fcpart[j] + bf1[j];
    o1[j] = (t > 0.f) ? t : 0.f;
    g_fcpart[j] = 0.f;              // restore zero invariant for next replay
    __syncthreads();
    float acc = bf2[j];
    for (int k = 0; k < 128; k++) acc += o1[k] * Wf2[(size_t)k * 128 + j];
    out[j] = (acc > 0.f) ? acc : 0.f;
}

// ---------------- launcher ----------------
extern "C" void kernel_launch(void* const* d_in, const int* in_sizes, int n_in,
                              void* d_out, int out_size) {
    const float* x    = (const float*)d_in[0];
    const void*  eix  = d_in[1];
    const float* emb  = (const float*)d_in[2];
    const float* W1   = (const float*)d_in[3];
    const float* b1   = (const float*)d_in[4];
    const float* W2   = (const float*)d_in[5];
    const float* b2   = (const float*)d_in[6];
    const float* W3   = (const float*)d_in[7];
    const float* b3   = (const float*)d_in[8];
    const float* W4   = (const float*)d_in[9];
    const float* b4   = (const float*)d_in[10];
    const float* W5   = (const float*)d_in[11];
    const float* b5   = (const float*)d_in[12];
    const float* Wf1  = (const float*)d_in[13];
    const float* bf1  = (const float*)d_in[14];
    const float* Wf2  = (const float*)d_in[15];
    const float* bf2  = (const float*)d_in[16];
    float* out = (float*)d_out;

    // Resolve device addresses (round-2 lesson: never pass a __device__ symbol
    // directly from host code — host shadow is ATS-dereferenceable).
    __half *p_fa = nullptr, *p_fb = nullptr;
    cudaGetSymbolAddress((void**)&p_fa, g_fa);
    cudaGetSymbolAddress((void**)&p_fb, g_fb);

    const int TB = 256;
    const int NB_N = (NN + TB - 1) / TB;             // 150
    const int NB_Q = (EE / 4 + TB - 1) / TB;         // 1198 (4 edges/thread)
    const int NB_W = (NN + 7) / 8;                   // 4792 (warp per node)
    const int NB_P = (NN * 32 + TB - 1) / TB;

    cudaStream_t s2;
    cudaStreamCreateWithFlags(&s2, cudaStreamNonBlocking);
    cudaEvent_t evFork, evScan, evPre, evScat, evClean;
    cudaEventCreateWithFlags(&evFork,  cudaEventDisableTiming);
    cudaEventCreateWithFlags(&evScan,  cudaEventDisableTiming);
    cudaEventCreateWithFlags(&evPre,   cudaEventDisableTiming);
    cudaEventCreateWithFlags(&evScat,  cudaEventDisableTiming);
    cudaEventCreateWithFlags(&evClean, cudaEventDisableTiming);

    // fork side stream: h0 build + gemm1 (edge-independent)
    cudaEventRecord(evFork, 0);
    cudaStreamWaitEvent(s2, evFork, 0);
    build_h0_kernel<<<NB_W, TB, 0, s2>>>(x, emb);
    gemm1_kernel<<<NB_N, TB, 0, s2>>>(W1);

    // main: histogram + parallel scan
    convert_hist_kernel<<<NB_Q, TB>>>(eix);
    scanP1_kernel<<<SCB, 256>>>();
    scanP2_kernel<<<1, 256>>>();
    scanP3_kernel<<<SCB, 256>>>();
    cudaEventRecord(evScan, 0);
    // side: prescale needs gemm1 (same stream) + dinv (evScan); overlaps scatter
    cudaStreamWaitEvent(s2, evScan, 0);
    prescale_kernel<<<NB_P, TB, 0, s2>>>();
    cudaEventRecord(evPre, s2);
    // main: scatter
    scatter_kernel<<<NB_Q, TB>>>(eix);
    cudaEventRecord(evScat, 0);
    // side: cleanup overlapped with agg chain
    cudaStreamWaitEvent(s2, evScat, 0);
    cleanup_kernel<<<NB_N, TB, 0, s2>>>();
    cudaEventRecord(evClean, s2);
    // main: join prescale, run fused GCN chain
    cudaStreamWaitEvent(0, evPre, 0);
    aggA_kernel<<<NB_W, TB>>>(b1, W2);                // -> g_fa
    aggB_kernel<0><<<NB_W, TB>>>(p_fa, b2, W3, p_fb); // -> g_fb
    aggB_kernel<1><<<NB_W, TB>>>(p_fb, b3, W4, p_fa); // -> g_fa
    aggD_kernel<<<NB_W, TB>>>(p_fa, b4, W5);          // -> g_s5
    agg5_kernel<<<NB_W, TB>>>(b5);                    // -> g_v

    // FC head (join cleanup before graph end)
    fc1_kernel<<<512, 128>>>(Wf1);
    cudaStreamWaitEvent(0, evClean, 0);
    fc2_kernel<<<1, 128>>>(bf1, Wf2, bf2, out);

    (void)in_sizes; (void)n_in; (void)out_size;
}